// round 3
// baseline (speedup 1.0000x reference)
#include <cuda_runtime.h>
#include <math.h>

#define N_TOK 16384
#define C_DIM 768
#define I_DIM 1536
#define E_EXP 16
#define SLOTS (3*N_TOK)   // 2N routed assignments + N shared

// ---------------- scratch (static device globals; no allocation) ----------------
__device__ int   g_counts[E_EXP];
__device__ int   g_offsets[E_EXP];
__device__ int   g_cursor[E_EXP];
__device__ int   g_re[N_TOK*2];
__device__ float g_rw[N_TOK*2];
__device__ int   g_ids[SLOTS];
__device__ float g_wt[SLOTS];
__device__ float g_G[SLOTS*(size_t)I_DIM];   // gate pre-activation   (~302 MB)
__device__ float g_H[SLOTS*(size_t)I_DIM];   // silu(G)*U             (~302 MB)

// ---------------- tiny setup kernels ----------------
__global__ void init_kernel() {
    int t = threadIdx.x;
    if (t < E_EXP) g_counts[t] = 0;
}

// one warp per token: logits -> top2 -> 2-way softmax weights
__global__ void router_kernel(const float* __restrict__ x,
                              const float* __restrict__ wgate,
                              const float* __restrict__ bias) {
    int warp = (blockIdx.x * blockDim.x + threadIdx.x) >> 5;
    int lane = threadIdx.x & 31;
    if (warp >= N_TOK) return;

    float acc = 0.f;
    if (lane < E_EXP) {
        const float* xr = x + (size_t)warp * C_DIM;
        #pragma unroll 8
        for (int c = 0; c < C_DIM; c++)
            acc = fmaf(xr[c], wgate[c * E_EXP + lane], acc);
        acc += bias[lane];
    }
    // top-2 (ties -> lowest index, matching lax.top_k)
    float l0 = -1e30f, l1 = -1e30f; int i0 = 0, i1 = 0;
    #pragma unroll
    for (int e = 0; e < E_EXP; e++) {
        float v = __shfl_sync(0xffffffffu, acc, e);
        if (v > l0)      { l1 = l0; i1 = i0; l0 = v; i0 = e; }
        else if (v > l1) { l1 = v;  i1 = e; }
    }
    if (lane == 0) {
        float w0 = 1.f / (1.f + __expf(l1 - l0));   // renormalized top-2 softmax
        g_re[warp*2+0] = i0; g_rw[warp*2+0] = w0;
        g_re[warp*2+1] = i1; g_rw[warp*2+1] = 1.f - w0;
        atomicAdd(&g_counts[i0], 1);
        atomicAdd(&g_counts[i1], 1);
    }
}

__global__ void scan_kernel() {
    if (threadIdx.x == 0) {
        int off = 0;
        for (int e = 0; e < E_EXP; e++) {
            g_offsets[e] = off;
            g_cursor[e]  = off;
            off += g_counts[e];
        }
    }
}

__global__ void fill_kernel() {
    int t = blockIdx.x * blockDim.x + threadIdx.x;
    if (t >= N_TOK) return;
    #pragma unroll
    for (int s = 0; s < 2; s++) {
        int e = g_re[t*2+s];
        int pos = atomicAdd(&g_cursor[e], 1);
        g_ids[pos] = t;
        g_wt[pos]  = g_rw[t*2+s];
    }
    // shared-expert identity region
    g_ids[2*N_TOK + t] = t;
    g_wt [2*N_TOK + t] = 1.f;
}

// ---------------- batched expert GEMM ----------------
// Tile: BM=64, BN=128, BK=16, 128 threads, 8x8 register tile / thread.
// AMODE 0: A = gather rows of x via g_ids           (K = C_DIM)
// AMODE 1: A = g_H rows, direct slot indexing       (K = I_DIM)
// EPI 0: store G            EPI 1: store H = silu(G)*acc
// EPI 2: atomicAdd w*acc -> out[token]   EPI 3: store acc -> out[token]
template<int AMODE, int EPI>
__global__ void __launch_bounds__(128)
moe_gemm(const float* __restrict__ Asrc,
         const float* __restrict__ Wr,     // (E, K, Nc) routed weights
         const float* __restrict__ Ws,     // (K, Nc)    shared weights
         float* __restrict__ outp,
         int K, int Nc, int zbase)
{
    int z = zbase + blockIdx.z;
    int cnt, base;
    const float* B;
    if (z == E_EXP) { cnt = N_TOK;      base = 2*N_TOK;      B = Ws; }
    else            { cnt = g_counts[z]; base = g_offsets[z]; B = Wr + (size_t)z * K * Nc; }

    int rb = blockIdx.y;
    if (rb * 64 >= cnt) return;
    int col0 = blockIdx.x * 128;

    __shared__ float As[16][68];    // [k][m], padded
    __shared__ float Bs[16][128];   // [k][n]

    int tid = threadIdx.x;
    int tx = tid & 15, ty = tid >> 4;

    // ---- A loader mapping: 2 float4 per thread (64 rows x 16 k) ----
    int lr    = tid >> 1;     // row in tile 0..63
    int lhalf = tid & 1;      // which 8-float half of the row
    int r_load = rb * 64 + lr;
    int rr = r_load < cnt ? r_load : cnt - 1;
    const float* arow;
    if (AMODE == 0) {
        int tok = g_ids[base + rr];
        arow = Asrc + (size_t)tok * K;
    } else {
        arow = g_H + (size_t)(base + rr) * K;
    }

    // ---- B loader mapping: 4 float4 per thread (16 k x 128 n) ----
    int bk = tid >> 3;        // 0..15
    int bc = tid & 7;         // float4 column group
    const float* bbase = B + col0;

    float4 va[2], vb[4];
    auto ldA = [&](int k0) {
        va[0] = *(const float4*)(arow + k0 + lhalf*8);
        va[1] = *(const float4*)(arow + k0 + lhalf*8 + 4);
    };
    auto ldB = [&](int k0) {
        const float* p = bbase + (size_t)(k0 + bk) * Nc + bc * 4;
        #pragma unroll
        for (int i = 0; i < 4; i++) vb[i] = *(const float4*)(p + i*32);
    };
    auto stA = [&]() {
        #pragma unroll
        for (int q = 0; q < 2; q++) {
            int kl = lhalf*8 + q*4;
            float4 v = va[q];
            As[kl+0][lr] = v.x; As[kl+1][lr] = v.y;
            As[kl+2][lr] = v.z; As[kl+3][lr] = v.w;
        }
    };
    auto stB = [&]() {
        #pragma unroll
        for (int i = 0; i < 4; i++)
            *(float4*)&Bs[bk][(bc + i*8)*4] = vb[i];
    };

    float acc[8][8];
    #pragma unroll
    for (int i = 0; i < 8; i++)
        #pragma unroll
        for (int j = 0; j < 8; j++) acc[i][j] = 0.f;

    ldA(0); ldB(0); stA(); stB();
    __syncthreads();

    int KT = K / 16;
    for (int kt = 0; kt < KT; ++kt) {
        if (kt + 1 < KT) { ldA((kt+1)*16); ldB((kt+1)*16); }   // prefetch to regs
        #pragma unroll
        for (int kk = 0; kk < 16; kk++) {
            float a[8], b[8];
            *(float4*)&a[0] = *(const float4*)&As[kk][ty*8];
            *(float4*)&a[4] = *(const float4*)&As[kk][ty*8 + 4];
            *(float4*)&b[0] = *(const float4*)&Bs[kk][tx*8];
            *(float4*)&b[4] = *(const float4*)&Bs[kk][tx*8 + 4];
            #pragma unroll
            for (int i = 0; i < 8; i++)
                #pragma unroll
                for (int j = 0; j < 8; j++)
                    acc[i][j] = fmaf(a[i], b[j], acc[i][j]);
        }
        __syncthreads();
        if (kt + 1 < KT) { stA(); stB(); __syncthreads(); }
    }

    // ---- epilogue ----
    int row0 = rb * 64 + ty * 8;
    #pragma unroll
    for (int i = 0; i < 8; i++) {
        int r = row0 + i;
        if (r >= cnt) continue;
        int slot = base + r;
        if (EPI == 0) {
            size_t cb = (size_t)slot * Nc + col0 + tx*8;
            *(float4*)&g_G[cb]   = make_float4(acc[i][0], acc[i][1], acc[i][2], acc[i][3]);
            *(float4*)&g_G[cb+4] = make_float4(acc[i][4], acc[i][5], acc[i][6], acc[i][7]);
        } else if (EPI == 1) {
            size_t cb = (size_t)slot * Nc + col0 + tx*8;
            float4 g0 = *(const float4*)&g_G[cb];
            float4 g1 = *(const float4*)&g_G[cb+4];
            float gg[8] = {g0.x, g0.y, g0.z, g0.w, g1.x, g1.y, g1.z, g1.w};
            float h[8];
            #pragma unroll
            for (int j = 0; j < 8; j++) {
                float s = gg[j] / (1.f + __expf(-gg[j]));   // silu
                h[j] = s * acc[i][j];
            }
            *(float4*)&g_H[cb]   = make_float4(h[0], h[1], h[2], h[3]);
            *(float4*)&g_H[cb+4] = make_float4(h[4], h[5], h[6], h[7]);
        } else {
            int tok = g_ids[slot];
            size_t ob = (size_t)tok * C_DIM + col0 + tx*8;
            if (EPI == 3) {
                *(float4*)&outp[ob]   = make_float4(acc[i][0], acc[i][1], acc[i][2], acc[i][3]);
                *(float4*)&outp[ob+4] = make_float4(acc[i][4], acc[i][5], acc[i][6], acc[i][7]);
            } else {
                float w = g_wt[slot];
                #pragma unroll
                for (int j = 0; j < 8; j++)
                    atomicAdd(&outp[ob + j], w * acc[i][j]);
            }
        }
    }
}

// ---------------- launch ----------------
extern "C" void kernel_launch(void* const* d_in, const int* in_sizes, int n_in,
                              void* d_out, int out_size) {
    const float* x    = (const float*)d_in[0];
    const float* wgt  = (const float*)d_in[1];
    const float* bias = (const float*)d_in[2];
    const float* wg   = (const float*)d_in[3];
    const float* wu   = (const float*)d_in[4];
    const float* wd   = (const float*)d_in[5];
    const float* swg  = (const float*)d_in[6];
    const float* swu  = (const float*)d_in[7];
    const float* swd  = (const float*)d_in[8];
    float* out = (float*)d_out;

    init_kernel<<<1, 32>>>();
    router_kernel<<<(N_TOK*32 + 255)/256, 256>>>(x, wgt, bias);
    scan_kernel<<<1, 1>>>();
    fill_kernel<<<(N_TOK + 255)/256, 256>>>();

    // G = X @ Wg   (17 "experts": 16 routed + shared)
    moe_gemm<0,0><<<dim3(I_DIM/128, N_TOK/64, 17), 128>>>(x, wg, swg, nullptr, C_DIM, I_DIM, 0);
    // H = silu(G) * (X @ Wu)
    moe_gemm<0,1><<<dim3(I_DIM/128, N_TOK/64, 17), 128>>>(x, wu, swu, nullptr, C_DIM, I_DIM, 0);
    // out = H_shared @ swd              (plain store, initializes d_out)
    moe_gemm<1,3><<<dim3(C_DIM/128, N_TOK/64, 1), 128>>>(nullptr, wd, swd, out, I_DIM, C_DIM, 16);
    // out += w * (H_e @ wd_e)           (atomicAdd, stream-ordered after the store pass)
    moe_gemm<1,2><<<dim3(C_DIM/128, N_TOK/64, 16), 128>>>(nullptr, wd, swd, out, I_DIM, C_DIM, 0);
}

// round 4
// speedup vs baseline: 1.0000x; 1.0000x over previous
#include <cuda_runtime.h>
#include <math.h>

#define N_TOK 16384
#define C_DIM 768
#define I_DIM 1536
#define E_EXP 16
#define SLOTS (3*N_TOK)   // 2N routed assignments + N shared

// ---------------- scratch (static device globals; no allocation) ----------------
__device__ int   g_counts[E_EXP];
__device__ int   g_offsets[E_EXP];
__device__ int   g_cursor[E_EXP];
__device__ int   g_re[N_TOK*2];
__device__ float g_rw[N_TOK*2];
__device__ int   g_ids[SLOTS];
__device__ float g_wt[SLOTS];
__device__ float g_G[SLOTS*(size_t)I_DIM];   // gate pre-activation   (~302 MB)
__device__ float g_H[SLOTS*(size_t)I_DIM];   // silu(G)*U             (~302 MB)

// ---------------- tiny setup kernels ----------------
__global__ void init_kernel() {
    int t = threadIdx.x;
    if (t < E_EXP) g_counts[t] = 0;
}

// one warp per token: logits -> top2 -> 2-way softmax weights
__global__ void router_kernel(const float* __restrict__ x,
                              const float* __restrict__ wgate,
                              const float* __restrict__ bias) {
    int warp = (blockIdx.x * blockDim.x + threadIdx.x) >> 5;
    int lane = threadIdx.x & 31;
    if (warp >= N_TOK) return;

    float acc = 0.f;
    if (lane < E_EXP) {
        const float* xr = x + (size_t)warp * C_DIM;
        #pragma unroll 8
        for (int c = 0; c < C_DIM; c++)
            acc = fmaf(xr[c], wgate[c * E_EXP + lane], acc);
        acc += bias[lane];
    }
    // top-2 (ties -> lowest index, matching lax.top_k)
    float l0 = -1e30f, l1 = -1e30f; int i0 = 0, i1 = 0;
    #pragma unroll
    for (int e = 0; e < E_EXP; e++) {
        float v = __shfl_sync(0xffffffffu, acc, e);
        if (v > l0)      { l1 = l0; i1 = i0; l0 = v; i0 = e; }
        else if (v > l1) { l1 = v;  i1 = e; }
    }
    if (lane == 0) {
        float w0 = 1.f / (1.f + __expf(l1 - l0));   // renormalized top-2 softmax
        g_re[warp*2+0] = i0; g_rw[warp*2+0] = w0;
        g_re[warp*2+1] = i1; g_rw[warp*2+1] = 1.f - w0;
        atomicAdd(&g_counts[i0], 1);
        atomicAdd(&g_counts[i1], 1);
    }
}

__global__ void scan_kernel() {
    if (threadIdx.x == 0) {
        int off = 0;
        for (int e = 0; e < E_EXP; e++) {
            g_offsets[e] = off;
            g_cursor[e]  = off;
            off += g_counts[e];
        }
    }
}

__global__ void fill_kernel() {
    int t = blockIdx.x * blockDim.x + threadIdx.x;
    if (t >= N_TOK) return;
    #pragma unroll
    for (int s = 0; s < 2; s++) {
        int e = g_re[t*2+s];
        int pos = atomicAdd(&g_cursor[e], 1);
        g_ids[pos] = t;
        g_wt[pos]  = g_rw[t*2+s];
    }
    // shared-expert identity region
    g_ids[2*N_TOK + t] = t;
    g_wt [2*N_TOK + t] = 1.f;
}

// ---------------- batched expert GEMM ----------------
// Tile: BM=64, BN=128, BK=16, 128 threads, 8x8 register tile / thread.
// AMODE 0: A = gather rows of x via g_ids           (K = C_DIM)
// AMODE 1: A = g_H rows, direct slot indexing       (K = I_DIM)
// EPI 0: store G            EPI 1: store H = silu(G)*acc
// EPI 2: atomicAdd w*acc -> out[token]   EPI 3: store acc -> out[token]
template<int AMODE, int EPI>
__global__ void __launch_bounds__(128)
moe_gemm(const float* __restrict__ Asrc,
         const float* __restrict__ Wr,     // (E, K, Nc) routed weights
         const float* __restrict__ Ws,     // (K, Nc)    shared weights
         float* __restrict__ outp,
         int K, int Nc, int zbase)
{
    int z = zbase + blockIdx.z;
    int cnt, base;
    const float* B;
    if (z == E_EXP) { cnt = N_TOK;      base = 2*N_TOK;      B = Ws; }
    else            { cnt = g_counts[z]; base = g_offsets[z]; B = Wr + (size_t)z * K * Nc; }

    int rb = blockIdx.y;
    if (rb * 64 >= cnt) return;
    int col0 = blockIdx.x * 128;

    __shared__ float As[16][68];    // [k][m], padded
    __shared__ float Bs[16][128];   // [k][n]

    int tid = threadIdx.x;
    int tx = tid & 15, ty = tid >> 4;

    // ---- A loader mapping: 2 float4 per thread (64 rows x 16 k) ----
    int lr    = tid >> 1;     // row in tile 0..63
    int lhalf = tid & 1;      // which 8-float half of the row
    int r_load = rb * 64 + lr;
    int rr = r_load < cnt ? r_load : cnt - 1;
    const float* arow;
    if (AMODE == 0) {
        int tok = g_ids[base + rr];
        arow = Asrc + (size_t)tok * K;
    } else {
        arow = g_H + (size_t)(base + rr) * K;
    }

    // ---- B loader mapping: 4 float4 per thread (16 k x 128 n) ----
    int bk = tid >> 3;        // 0..15
    int bc = tid & 7;         // float4 column group
    const float* bbase = B + col0;

    float4 va[2], vb[4];
    auto ldA = [&](int k0) {
        va[0] = *(const float4*)(arow + k0 + lhalf*8);
        va[1] = *(const float4*)(arow + k0 + lhalf*8 + 4);
    };
    auto ldB = [&](int k0) {
        const float* p = bbase + (size_t)(k0 + bk) * Nc + bc * 4;
        #pragma unroll
        for (int i = 0; i < 4; i++) vb[i] = *(const float4*)(p + i*32);
    };
    auto stA = [&]() {
        #pragma unroll
        for (int q = 0; q < 2; q++) {
            int kl = lhalf*8 + q*4;
            float4 v = va[q];
            As[kl+0][lr] = v.x; As[kl+1][lr] = v.y;
            As[kl+2][lr] = v.z; As[kl+3][lr] = v.w;
        }
    };
    auto stB = [&]() {
        #pragma unroll
        for (int i = 0; i < 4; i++)
            *(float4*)&Bs[bk][(bc + i*8)*4] = vb[i];
    };

    float acc[8][8];
    #pragma unroll
    for (int i = 0; i < 8; i++)
        #pragma unroll
        for (int j = 0; j < 8; j++) acc[i][j] = 0.f;

    ldA(0); ldB(0); stA(); stB();
    __syncthreads();

    int KT = K / 16;
    for (int kt = 0; kt < KT; ++kt) {
        if (kt + 1 < KT) { ldA((kt+1)*16); ldB((kt+1)*16); }   // prefetch to regs
        #pragma unroll
        for (int kk = 0; kk < 16; kk++) {
            float a[8], b[8];
            *(float4*)&a[0] = *(const float4*)&As[kk][ty*8];
            *(float4*)&a[4] = *(const float4*)&As[kk][ty*8 + 4];
            *(float4*)&b[0] = *(const float4*)&Bs[kk][tx*8];
            *(float4*)&b[4] = *(const float4*)&Bs[kk][tx*8 + 4];
            #pragma unroll
            for (int i = 0; i < 8; i++)
                #pragma unroll
                for (int j = 0; j < 8; j++)
                    acc[i][j] = fmaf(a[i], b[j], acc[i][j]);
        }
        __syncthreads();
        if (kt + 1 < KT) { stA(); stB(); __syncthreads(); }
    }

    // ---- epilogue ----
    int row0 = rb * 64 + ty * 8;
    #pragma unroll
    for (int i = 0; i < 8; i++) {
        int r = row0 + i;
        if (r >= cnt) continue;
        int slot = base + r;
        if (EPI == 0) {
            size_t cb = (size_t)slot * Nc + col0 + tx*8;
            *(float4*)&g_G[cb]   = make_float4(acc[i][0], acc[i][1], acc[i][2], acc[i][3]);
            *(float4*)&g_G[cb+4] = make_float4(acc[i][4], acc[i][5], acc[i][6], acc[i][7]);
        } else if (EPI == 1) {
            size_t cb = (size_t)slot * Nc + col0 + tx*8;
            float4 g0 = *(const float4*)&g_G[cb];
            float4 g1 = *(const float4*)&g_G[cb+4];
            float gg[8] = {g0.x, g0.y, g0.z, g0.w, g1.x, g1.y, g1.z, g1.w};
            float h[8];
            #pragma unroll
            for (int j = 0; j < 8; j++) {
                float s = gg[j] / (1.f + __expf(-gg[j]));   // silu
                h[j] = s * acc[i][j];
            }
            *(float4*)&g_H[cb]   = make_float4(h[0], h[1], h[2], h[3]);
            *(float4*)&g_H[cb+4] = make_float4(h[4], h[5], h[6], h[7]);
        } else {
            int tok = g_ids[slot];
            size_t ob = (size_t)tok * C_DIM + col0 + tx*8;
            if (EPI == 3) {
                *(float4*)&outp[ob]   = make_float4(acc[i][0], acc[i][1], acc[i][2], acc[i][3]);
                *(float4*)&outp[ob+4] = make_float4(acc[i][4], acc[i][5], acc[i][6], acc[i][7]);
            } else {
                float w = g_wt[slot];
                #pragma unroll
                for (int j = 0; j < 8; j++)
                    atomicAdd(&outp[ob + j], w * acc[i][j]);
            }
        }
    }
}

// ---------------- launch ----------------
extern "C" void kernel_launch(void* const* d_in, const int* in_sizes, int n_in,
                              void* d_out, int out_size) {
    const float* x    = (const float*)d_in[0];
    const float* wgt  = (const float*)d_in[1];
    const float* bias = (const float*)d_in[2];
    const float* wg   = (const float*)d_in[3];
    const float* wu   = (const float*)d_in[4];
    const float* wd   = (const float*)d_in[5];
    const float* swg  = (const float*)d_in[6];
    const float* swu  = (const float*)d_in[7];
    const float* swd  = (const float*)d_in[8];
    float* out = (float*)d_out;

    init_kernel<<<1, 32>>>();
    router_kernel<<<(N_TOK*32 + 255)/256, 256>>>(x, wgt, bias);
    scan_kernel<<<1, 1>>>();
    fill_kernel<<<(N_TOK + 255)/256, 256>>>();

    // G = X @ Wg   (17 "experts": 16 routed + shared)
    moe_gemm<0,0><<<dim3(I_DIM/128, N_TOK/64, 17), 128>>>(x, wg, swg, nullptr, C_DIM, I_DIM, 0);
    // H = silu(G) * (X @ Wu)
    moe_gemm<0,1><<<dim3(I_DIM/128, N_TOK/64, 17), 128>>>(x, wu, swu, nullptr, C_DIM, I_DIM, 0);
    // out = H_shared @ swd              (plain store, initializes d_out)
    moe_gemm<1,3><<<dim3(C_DIM/128, N_TOK/64, 1), 128>>>(nullptr, wd, swd, out, I_DIM, C_DIM, 16);
    // out += w * (H_e @ wd_e)           (atomicAdd, stream-ordered after the store pass)
    moe_gemm<1,2><<<dim3(C_DIM/128, N_TOK/64, 16), 128>>>(nullptr, wd, swd, out, I_DIM, C_DIM, 0);
}

// round 5
// speedup vs baseline: 1.0004x; 1.0003x over previous
#include <cuda_runtime.h>
#include <math.h>

#define N_TOK 16384
#define C_DIM 768
#define I_DIM 1536
#define E_EXP 16
#define SLOTS (3*N_TOK)   // 2N routed assignments + N shared

// ---------------- scratch (static device globals; no allocation) ----------------
__device__ int   g_counts[E_EXP];
__device__ int   g_offsets[E_EXP];
__device__ int   g_cursor[E_EXP];
__device__ int   g_re[N_TOK*2];
__device__ float g_rw[N_TOK*2];
__device__ int   g_ids[SLOTS];
__device__ float g_wt[SLOTS];
__device__ float g_G[SLOTS*(size_t)I_DIM];   // gate pre-activation   (~302 MB)
__device__ float g_H[SLOTS*(size_t)I_DIM];   // silu(G)*U             (~302 MB)

// ---------------- tiny setup kernels ----------------
__global__ void init_kernel() {
    int t = threadIdx.x;
    if (t < E_EXP) g_counts[t] = 0;
}

// one warp per token: logits -> top2 -> 2-way softmax weights
__global__ void router_kernel(const float* __restrict__ x,
                              const float* __restrict__ wgate,
                              const float* __restrict__ bias) {
    int warp = (blockIdx.x * blockDim.x + threadIdx.x) >> 5;
    int lane = threadIdx.x & 31;
    if (warp >= N_TOK) return;

    float acc = 0.f;
    if (lane < E_EXP) {
        const float* xr = x + (size_t)warp * C_DIM;
        #pragma unroll 8
        for (int c = 0; c < C_DIM; c++)
            acc = fmaf(xr[c], wgate[c * E_EXP + lane], acc);
        acc += bias[lane];
    }
    // top-2 (ties -> lowest index, matching lax.top_k)
    float l0 = -1e30f, l1 = -1e30f; int i0 = 0, i1 = 0;
    #pragma unroll
    for (int e = 0; e < E_EXP; e++) {
        float v = __shfl_sync(0xffffffffu, acc, e);
        if (v > l0)      { l1 = l0; i1 = i0; l0 = v; i0 = e; }
        else if (v > l1) { l1 = v;  i1 = e; }
    }
    if (lane == 0) {
        float w0 = 1.f / (1.f + __expf(l1 - l0));   // renormalized top-2 softmax
        g_re[warp*2+0] = i0; g_rw[warp*2+0] = w0;
        g_re[warp*2+1] = i1; g_rw[warp*2+1] = 1.f - w0;
        atomicAdd(&g_counts[i0], 1);
        atomicAdd(&g_counts[i1], 1);
    }
}

__global__ void scan_kernel() {
    if (threadIdx.x == 0) {
        int off = 0;
        for (int e = 0; e < E_EXP; e++) {
            g_offsets[e] = off;
            g_cursor[e]  = off;
            off += g_counts[e];
        }
    }
}

__global__ void fill_kernel() {
    int t = blockIdx.x * blockDim.x + threadIdx.x;
    if (t >= N_TOK) return;
    #pragma unroll
    for (int s = 0; s < 2; s++) {
        int e = g_re[t*2+s];
        int pos = atomicAdd(&g_cursor[e], 1);
        g_ids[pos] = t;
        g_wt[pos]  = g_rw[t*2+s];
    }
    // shared-expert identity region
    g_ids[2*N_TOK + t] = t;
    g_wt [2*N_TOK + t] = 1.f;
}

// ---------------- batched expert GEMM ----------------
// Tile: BM=64, BN=128, BK=16, 128 threads, 8x8 register tile / thread.
// AMODE 0: A = gather rows of x via g_ids           (K = C_DIM)
// AMODE 1: A = g_H rows, direct slot indexing       (K = I_DIM)
// EPI 0: store G            EPI 1: store H = silu(G)*acc
// EPI 2: atomicAdd w*acc -> out[token]   EPI 3: store acc -> out[token]
template<int AMODE, int EPI>
__global__ void __launch_bounds__(128)
moe_gemm(const float* __restrict__ Asrc,
         const float* __restrict__ Wr,     // (E, K, Nc) routed weights
         const float* __restrict__ Ws,     // (K, Nc)    shared weights
         float* __restrict__ outp,
         int K, int Nc, int zbase)
{
    int z = zbase + blockIdx.z;
    int cnt, base;
    const float* B;
    if (z == E_EXP) { cnt = N_TOK;      base = 2*N_TOK;      B = Ws; }
    else            { cnt = g_counts[z]; base = g_offsets[z]; B = Wr + (size_t)z * K * Nc; }

    int rb = blockIdx.y;
    if (rb * 64 >= cnt) return;
    int col0 = blockIdx.x * 128;

    __shared__ float As[16][68];    // [k][m], padded
    __shared__ float Bs[16][128];   // [k][n]

    int tid = threadIdx.x;
    int tx = tid & 15, ty = tid >> 4;

    // ---- A loader mapping: 2 float4 per thread (64 rows x 16 k) ----
    int lr    = tid >> 1;     // row in tile 0..63
    int lhalf = tid & 1;      // which 8-float half of the row
    int r_load = rb * 64 + lr;
    int rr = r_load < cnt ? r_load : cnt - 1;
    const float* arow;
    if (AMODE == 0) {
        int tok = g_ids[base + rr];
        arow = Asrc + (size_t)tok * K;
    } else {
        arow = g_H + (size_t)(base + rr) * K;
    }

    // ---- B loader mapping: 4 float4 per thread (16 k x 128 n) ----
    int bk = tid >> 3;        // 0..15
    int bc = tid & 7;         // float4 column group
    const float* bbase = B + col0;

    float4 va[2], vb[4];
    auto ldA = [&](int k0) {
        va[0] = *(const float4*)(arow + k0 + lhalf*8);
        va[1] = *(const float4*)(arow + k0 + lhalf*8 + 4);
    };
    auto ldB = [&](int k0) {
        const float* p = bbase + (size_t)(k0 + bk) * Nc + bc * 4;
        #pragma unroll
        for (int i = 0; i < 4; i++) vb[i] = *(const float4*)(p + i*32);
    };
    auto stA = [&]() {
        #pragma unroll
        for (int q = 0; q < 2; q++) {
            int kl = lhalf*8 + q*4;
            float4 v = va[q];
            As[kl+0][lr] = v.x; As[kl+1][lr] = v.y;
            As[kl+2][lr] = v.z; As[kl+3][lr] = v.w;
        }
    };
    auto stB = [&]() {
        #pragma unroll
        for (int i = 0; i < 4; i++)
            *(float4*)&Bs[bk][(bc + i*8)*4] = vb[i];
    };

    float acc[8][8];
    #pragma unroll
    for (int i = 0; i < 8; i++)
        #pragma unroll
        for (int j = 0; j < 8; j++) acc[i][j] = 0.f;

    ldA(0); ldB(0); stA(); stB();
    __syncthreads();

    int KT = K / 16;
    for (int kt = 0; kt < KT; ++kt) {
        if (kt + 1 < KT) { ldA((kt+1)*16); ldB((kt+1)*16); }   // prefetch to regs
        #pragma unroll
        for (int kk = 0; kk < 16; kk++) {
            float a[8], b[8];
            *(float4*)&a[0] = *(const float4*)&As[kk][ty*8];
            *(float4*)&a[4] = *(const float4*)&As[kk][ty*8 + 4];
            *(float4*)&b[0] = *(const float4*)&Bs[kk][tx*8];
            *(float4*)&b[4] = *(const float4*)&Bs[kk][tx*8 + 4];
            #pragma unroll
            for (int i = 0; i < 8; i++)
                #pragma unroll
                for (int j = 0; j < 8; j++)
                    acc[i][j] = fmaf(a[i], b[j], acc[i][j]);
        }
        __syncthreads();
        if (kt + 1 < KT) { stA(); stB(); __syncthreads(); }
    }

    // ---- epilogue ----
    int row0 = rb * 64 + ty * 8;
    #pragma unroll
    for (int i = 0; i < 8; i++) {
        int r = row0 + i;
        if (r >= cnt) continue;
        int slot = base + r;
        if (EPI == 0) {
            size_t cb = (size_t)slot * Nc + col0 + tx*8;
            *(float4*)&g_G[cb]   = make_float4(acc[i][0], acc[i][1], acc[i][2], acc[i][3]);
            *(float4*)&g_G[cb+4] = make_float4(acc[i][4], acc[i][5], acc[i][6], acc[i][7]);
        } else if (EPI == 1) {
            size_t cb = (size_t)slot * Nc + col0 + tx*8;
            float4 g0 = *(const float4*)&g_G[cb];
            float4 g1 = *(const float4*)&g_G[cb+4];
            float gg[8] = {g0.x, g0.y, g0.z, g0.w, g1.x, g1.y, g1.z, g1.w};
            float h[8];
            #pragma unroll
            for (int j = 0; j < 8; j++) {
                float s = gg[j] / (1.f + __expf(-gg[j]));   // silu
                h[j] = s * acc[i][j];
            }
            *(float4*)&g_H[cb]   = make_float4(h[0], h[1], h[2], h[3]);
            *(float4*)&g_H[cb+4] = make_float4(h[4], h[5], h[6], h[7]);
        } else {
            int tok = g_ids[slot];
            size_t ob = (size_t)tok * C_DIM + col0 + tx*8;
            if (EPI == 3) {
                *(float4*)&outp[ob]   = make_float4(acc[i][0], acc[i][1], acc[i][2], acc[i][3]);
                *(float4*)&outp[ob+4] = make_float4(acc[i][4], acc[i][5], acc[i][6], acc[i][7]);
            } else {
                float w = g_wt[slot];
                #pragma unroll
                for (int j = 0; j < 8; j++)
                    atomicAdd(&outp[ob + j], w * acc[i][j]);
            }
        }
    }
}

// ---------------- launch ----------------
extern "C" void kernel_launch(void* const* d_in, const int* in_sizes, int n_in,
                              void* d_out, int out_size) {
    const float* x    = (const float*)d_in[0];
    const float* wgt  = (const float*)d_in[1];
    const float* bias = (const float*)d_in[2];
    const float* wg   = (const float*)d_in[3];
    const float* wu   = (const float*)d_in[4];
    const float* wd   = (const float*)d_in[5];
    const float* swg  = (const float*)d_in[6];
    const float* swu  = (const float*)d_in[7];
    const float* swd  = (const float*)d_in[8];
    float* out = (float*)d_out;

    init_kernel<<<1, 32>>>();
    router_kernel<<<(N_TOK*32 + 255)/256, 256>>>(x, wgt, bias);
    scan_kernel<<<1, 1>>>();
    fill_kernel<<<(N_TOK + 255)/256, 256>>>();

    // G = X @ Wg   (17 "experts": 16 routed + shared)
    moe_gemm<0,0><<<dim3(I_DIM/128, N_TOK/64, 17), 128>>>(x, wg, swg, nullptr, C_DIM, I_DIM, 0);
    // H = silu(G) * (X @ Wu)
    moe_gemm<0,1><<<dim3(I_DIM/128, N_TOK/64, 17), 128>>>(x, wu, swu, nullptr, C_DIM, I_DIM, 0);
    // out = H_shared @ swd              (plain store, initializes d_out)
    moe_gemm<1,3><<<dim3(C_DIM/128, N_TOK/64, 1), 128>>>(nullptr, wd, swd, out, I_DIM, C_DIM, 16);
    // out += w * (H_e @ wd_e)           (atomicAdd, stream-ordered after the store pass)
    moe_gemm<1,2><<<dim3(C_DIM/128, N_TOK/64, 16), 128>>>(nullptr, wd, swd, out, I_DIM, C_DIM, 0);
}

// round 7
// speedup vs baseline: 1.7621x; 1.7615x over previous
#include <cuda_runtime.h>
#include <cuda_bf16.h>
#include <math.h>
#include <stdint.h>

#define N_TOK 16384
#define C_DIM 768
#define I_DIM 1536
#define E_EXP 16
#define E_ALL 17
#define SLOTS (3*N_TOK)
#define TILE_B 16384
#define STAGE_F (6*TILE_B)
#define STAGE_D (4*TILE_B)
#define SMEM_F (2*STAGE_F + 1024)
#define SMEM_D (2*STAGE_D + 1024)

// ---------------- static device scratch ----------------
__device__ int   g_counts[E_EXP];
__device__ int   g_offsets[E_EXP];
__device__ int   g_cursor[E_EXP];
__device__ int   g_re[N_TOK*2];
__device__ float g_rw[N_TOK*2];
__device__ int   g_ids[SLOTS];
__device__ float g_wt[SLOTS];
__device__ int   g_slot_of[N_TOK*2];

__device__ __nv_bfloat16 g_xh[(size_t)N_TOK*C_DIM];
__device__ __nv_bfloat16 g_xl[(size_t)N_TOK*C_DIM];
__device__ __nv_bfloat16 g_gh[(size_t)E_ALL*I_DIM*C_DIM];  // [(e*I+n)*C+k]
__device__ __nv_bfloat16 g_gl[(size_t)E_ALL*I_DIM*C_DIM];
__device__ __nv_bfloat16 g_uh[(size_t)E_ALL*I_DIM*C_DIM];
__device__ __nv_bfloat16 g_ul[(size_t)E_ALL*I_DIM*C_DIM];
__device__ __nv_bfloat16 g_dh[(size_t)E_ALL*C_DIM*I_DIM];  // [(e*C+n)*I+k]
__device__ __nv_bfloat16 g_dl[(size_t)E_ALL*C_DIM*I_DIM];
__device__ __nv_bfloat16 g_hh[(size_t)SLOTS*I_DIM];
__device__ __nv_bfloat16 g_hl[(size_t)SLOTS*I_DIM];
__device__ float g_O[(size_t)SLOTS*C_DIM];

// ---------------- PTX helpers (base ISA only: compute_103-safe) ----------------
__device__ __forceinline__ uint32_t smem_u32(const void* p){
    uint32_t a;
    asm("{ .reg .u64 t; cvta.to.shared.u64 t, %1; cvt.u32.u64 %0, t; }" : "=r"(a) : "l"(p));
    return a;
}
__device__ __forceinline__ void cp_row(uint32_t sbase, const void* src, int t){
    #pragma unroll
    for (int ch = 0; ch < 8; ch++){
        uint32_t off = (uint32_t)t*128u + (uint32_t)ch*16u;
        uint32_t dst = sbase + (off ^ ((off >> 3) & 0x70u));
        asm volatile("cp.async.cg.shared.global [%0], [%1], 16;"
            :: "r"(dst), "l"((const char*)src + ch*16) : "memory");
    }
}
__device__ __forceinline__ void cp_commit(){ asm volatile("cp.async.commit_group;" ::: "memory"); }
__device__ __forceinline__ void cp_wait1(){ asm volatile("cp.async.wait_group 1;" ::: "memory"); }
__device__ __forceinline__ void cp_wait0(){ asm volatile("cp.async.wait_group 0;" ::: "memory"); }

__device__ __forceinline__ void ldsm4(uint32_t* r, uint32_t addr){
    asm volatile("ldmatrix.sync.aligned.m8n8.x4.shared.b16 {%0,%1,%2,%3}, [%4];"
        : "=r"(r[0]), "=r"(r[1]), "=r"(r[2]), "=r"(r[3]) : "r"(addr));
}
__device__ __forceinline__ void hmma(float* d, const uint32_t* a, const uint32_t* b){
    asm volatile("mma.sync.aligned.m16n8k16.row.col.f32.bf16.bf16.f32 "
        "{%0,%1,%2,%3}, {%4,%5,%6,%7}, {%8,%9}, {%0,%1,%2,%3};"
        : "+f"(d[0]), "+f"(d[1]), "+f"(d[2]), "+f"(d[3])
        : "r"(a[0]), "r"(a[1]), "r"(a[2]), "r"(a[3]), "r"(b[0]), "r"(b[1]));
}

// ---------------- setup kernels ----------------
__global__ void init_kernel(){ if (threadIdx.x < E_EXP) g_counts[threadIdx.x] = 0; }

__global__ void router_kernel(const float* __restrict__ x, const float* __restrict__ wgate,
                              const float* __restrict__ bias){
    int warp = (blockIdx.x * blockDim.x + threadIdx.x) >> 5;
    int lane = threadIdx.x & 31;
    if (warp >= N_TOK) return;
    float acc = 0.f;
    if (lane < E_EXP){
        const float* xr = x + (size_t)warp * C_DIM;
        #pragma unroll 8
        for (int c = 0; c < C_DIM; c++) acc = fmaf(xr[c], wgate[c*E_EXP + lane], acc);
        acc += bias[lane];
    }
    float l0 = -1e30f, l1 = -1e30f; int i0 = 0, i1 = 0;
    #pragma unroll
    for (int e = 0; e < E_EXP; e++){
        float v = __shfl_sync(0xffffffffu, acc, e);
        if (v > l0)      { l1 = l0; i1 = i0; l0 = v; i0 = e; }
        else if (v > l1) { l1 = v;  i1 = e; }
    }
    if (lane == 0){
        float w0 = 1.f / (1.f + __expf(l1 - l0));
        g_re[warp*2+0] = i0; g_rw[warp*2+0] = w0;
        g_re[warp*2+1] = i1; g_rw[warp*2+1] = 1.f - w0;
        atomicAdd(&g_counts[i0], 1); atomicAdd(&g_counts[i1], 1);
    }
}

__global__ void scan_kernel(){
    if (threadIdx.x == 0){
        int off = 0;
        for (int e = 0; e < E_EXP; e++){ g_offsets[e] = off; g_cursor[e] = off; off += g_counts[e]; }
    }
}

__global__ void fill_kernel(){
    int t = blockIdx.x * blockDim.x + threadIdx.x;
    if (t >= N_TOK) return;
    #pragma unroll
    for (int s = 0; s < 2; s++){
        int e = g_re[t*2+s];
        int pos = atomicAdd(&g_cursor[e], 1);
        g_ids[pos] = t; g_wt[pos] = g_rw[t*2+s]; g_slot_of[t*2+s] = pos;
    }
    g_ids[2*N_TOK + t] = t; g_wt[2*N_TOK + t] = 1.f;
}

__global__ void split_x_kernel(const float* __restrict__ x){
    size_t i = (size_t)blockIdx.x * blockDim.x + threadIdx.x;
    if (i >= (size_t)N_TOK*C_DIM) return;
    float v = x[i];
    __nv_bfloat16 h = __float2bfloat16(v);
    g_xh[i] = h; g_xl[i] = __float2bfloat16(v - __bfloat162float(h));
}

// split + transpose: W (per expert (K,N) row-major) -> out[(e*N+n)*K + k]
__global__ void split_T_kernel(const float* __restrict__ W, int which, int ebase, int K, int N){
    __shared__ float t[32][33];
    int e = ebase + blockIdx.z;
    const float* Win = W + (size_t)blockIdx.z * K * N;
    int n0 = blockIdx.x*32, k0 = blockIdx.y*32;
    int tx = threadIdx.x, ty = threadIdx.y;   // (32,8)
    #pragma unroll
    for (int i = 0; i < 4; i++)
        t[ty + i*8][tx] = Win[(size_t)(k0 + ty + i*8)*N + n0 + tx];
    __syncthreads();
    __nv_bfloat16 *oh, *ol;
    if (which == 0){ oh = g_gh; ol = g_gl; }
    else if (which == 1){ oh = g_uh; ol = g_ul; }
    else { oh = g_dh; ol = g_dl; }
    #pragma unroll
    for (int i = 0; i < 4; i++){
        int n = n0 + ty + i*8;
        float v = t[tx][ty + i*8];
        size_t o = ((size_t)e*N + n)*K + k0 + tx;
        __nv_bfloat16 h = __float2bfloat16(v);
        oh[o] = h; ol[o] = __float2bfloat16(v - __bfloat162float(h));
    }
}

// ---------------- fused gate+up HMMA kernel ----------------
// CTA: 256 thr (8 warps), tile M=128 x N=128, K-chunk 64 bf16 (128B SW128 rows).
// Stage tiles: 0=Ah 1=Al 2=Gh 3=Gl 4=Uh 5=Ul. Double buffered.
__global__ void __launch_bounds__(256) fused_gateup_kernel(){
    int z = blockIdx.z, cnt, base;
    if (z == E_EXP){ cnt = N_TOK; base = 2*N_TOK; }
    else           { cnt = g_counts[z]; base = g_offsets[z]; }
    int rb = blockIdx.y;
    if (rb*128 >= cnt) return;
    int n0 = blockIdx.x * 128;

    extern __shared__ char smem[];
    uint32_t sb = (smem_u32(smem) + 1023u) & ~1023u;
    int tid = threadIdx.x, lane = tid & 31, wid = tid >> 5;
    int warp_m = wid >> 2, warp_n = wid & 3;   // 2 x 4

    // loader: 3 (tile,row) pairs per thread
    const char* lsrc[3]; uint32_t ltile[3]; int lrow[3];
    #pragma unroll
    for (int j = 0; j < 3; j++){
        int q = tid + j*256, tile = q >> 7, row = q & 127;
        const char* p;
        if (tile < 2){
            int r = rb*128 + row; int rr = r < cnt ? r : cnt - 1;
            int tok = g_ids[base + rr];
            p = (const char*)((tile == 0 ? g_xh : g_xl) + (size_t)tok*C_DIM);
        } else {
            size_t wr = ((size_t)z*I_DIM + n0 + row)*C_DIM;
            const __nv_bfloat16* w = tile==2 ? g_gh : tile==3 ? g_gl : tile==4 ? g_uh : g_ul;
            p = (const char*)(w + wr);
        }
        lsrc[j] = p; ltile[j] = (uint32_t)tile*TILE_B; lrow[j] = row;
    }
    auto load_stage = [&](int s, int kt){
        uint32_t st = sb + (uint32_t)s*STAGE_F;
        #pragma unroll
        for (int j = 0; j < 3; j++)
            cp_row(st + ltile[j], lsrc[j] + kt*128, lrow[j]);
        cp_commit();
    };

    // ldmatrix per-lane geometry
    int mat = lane >> 3;
    uint32_t xm = (uint32_t)(lane & 7) << 4;
    uint32_t rA[4], rB[2];
    #pragma unroll
    for (int mt = 0; mt < 4; mt++)
        rA[mt] = (uint32_t)(warp_m*64 + mt*16 + (mat & 1)*8 + (lane & 7)) << 7;
    #pragma unroll
    for (int ntp = 0; ntp < 2; ntp++)
        rB[ntp] = (uint32_t)(warp_n*32 + ntp*16 + ((mat >> 1) & 1)*8 + (lane & 7)) << 7;
    uint32_t caK = (uint32_t)((mat >> 1) & 1) * 16;
    uint32_t cbK = (uint32_t)(mat & 1) * 16;

    float ag[4][4][4], au[4][4][4];
    #pragma unroll
    for (int a = 0; a < 4; a++)
        #pragma unroll
        for (int b = 0; b < 4; b++)
            #pragma unroll
            for (int c = 0; c < 4; c++){ ag[a][b][c] = 0.f; au[a][b][c] = 0.f; }

    const int KT = C_DIM/64;   // 12
    load_stage(0, 0);
    load_stage(1, 1);

    for (int kt = 0; kt < KT; kt++){
        if (kt + 1 < KT) cp_wait1(); else cp_wait0();
        __syncthreads();
        uint32_t st = sb + (uint32_t)(kt & 1)*STAGE_F;
        uint32_t Ah = st, Al = st + TILE_B;
        uint32_t Gh = st + 2*TILE_B, Gl = st + 3*TILE_B;
        uint32_t Uh = st + 4*TILE_B, Ul = st + 5*TILE_B;
        #pragma unroll
        for (int ks = 0; ks < 4; ks++){
            uint32_t cA = ((uint32_t)ks*32 + caK) ^ xm;
            uint32_t cB = ((uint32_t)ks*32 + cbK) ^ xm;
            uint32_t fah[4][4], fal[4][4];
            #pragma unroll
            for (int mt = 0; mt < 4; mt++){
                ldsm4(fah[mt], Ah + rA[mt] + cA);
                ldsm4(fal[mt], Al + rA[mt] + cA);
            }
            uint32_t bh[2][4], bl[2][4];
            #pragma unroll
            for (int p = 0; p < 2; p++){ ldsm4(bh[p], Gh + rB[p] + cB); ldsm4(bl[p], Gl + rB[p] + cB); }
            #pragma unroll
            for (int mt = 0; mt < 4; mt++)
                #pragma unroll
                for (int nt = 0; nt < 4; nt++){
                    const uint32_t* b0 = &bh[nt>>1][(nt&1)*2];
                    const uint32_t* b1 = &bl[nt>>1][(nt&1)*2];
                    hmma(ag[mt][nt], fah[mt], b0);
                    hmma(ag[mt][nt], fah[mt], b1);
                    hmma(ag[mt][nt], fal[mt], b0);
                }
            #pragma unroll
            for (int p = 0; p < 2; p++){ ldsm4(bh[p], Uh + rB[p] + cB); ldsm4(bl[p], Ul + rB[p] + cB); }
            #pragma unroll
            for (int mt = 0; mt < 4; mt++)
                #pragma unroll
                for (int nt = 0; nt < 4; nt++){
                    const uint32_t* b0 = &bh[nt>>1][(nt&1)*2];
                    const uint32_t* b1 = &bl[nt>>1][(nt&1)*2];
                    hmma(au[mt][nt], fah[mt], b0);
                    hmma(au[mt][nt], fah[mt], b1);
                    hmma(au[mt][nt], fal[mt], b0);
                }
        }
        __syncthreads();
        if (kt + 2 < KT) load_stage(kt & 1, kt + 2);
    }

    // epilogue: h = silu(g)*u -> bf16 hi/lo planes
    int qr = lane >> 2, qc = (lane & 3)*2;
    #pragma unroll
    for (int mt = 0; mt < 4; mt++)
        #pragma unroll
        for (int h2 = 0; h2 < 2; h2++){
            int gr = rb*128 + warp_m*64 + mt*16 + h2*8 + qr;
            if (gr >= cnt) continue;
            size_t slot = (size_t)base + gr;
            #pragma unroll
            for (int nt = 0; nt < 4; nt++){
                float g0 = ag[mt][nt][h2*2+0], g1 = ag[mt][nt][h2*2+1];
                float u0 = au[mt][nt][h2*2+0], u1 = au[mt][nt][h2*2+1];
                float h0 = (g0 / (1.f + __expf(-g0))) * u0;
                float h1 = (g1 / (1.f + __expf(-g1))) * u1;
                __nv_bfloat16 h0h = __float2bfloat16(h0), h1h = __float2bfloat16(h1);
                __nv_bfloat162 vh; vh.x = h0h; vh.y = h1h;
                __nv_bfloat162 vl;
                vl.x = __float2bfloat16(h0 - __bfloat162float(h0h));
                vl.y = __float2bfloat16(h1 - __bfloat162float(h1h));
                size_t col = (size_t)n0 + warp_n*32 + nt*8 + qc;
                *(__nv_bfloat162*)(g_hh + slot*I_DIM + col) = vh;
                *(__nv_bfloat162*)(g_hl + slot*I_DIM + col) = vl;
            }
        }
}

// ---------------- down-projection HMMA kernel ----------------
__global__ void __launch_bounds__(256) down_proj_kernel(){
    int z = blockIdx.z, cnt, base;
    if (z == E_EXP){ cnt = N_TOK; base = 2*N_TOK; }
    else           { cnt = g_counts[z]; base = g_offsets[z]; }
    int rb = blockIdx.y;
    if (rb*128 >= cnt) return;
    int n0 = blockIdx.x * 128;

    extern __shared__ char smem[];
    uint32_t sb = (smem_u32(smem) + 1023u) & ~1023u;
    int tid = threadIdx.x, lane = tid & 31, wid = tid >> 5;
    int warp_m = wid >> 2, warp_n = wid & 3;

    const char* lsrc[2]; uint32_t ltile[2]; int lrow[2];
    #pragma unroll
    for (int j = 0; j < 2; j++){
        int q = tid + j*256, tile = q >> 7, row = q & 127;
        const char* p;
        if (tile < 2){
            int r = rb*128 + row; int rr = r < cnt ? r : cnt - 1;
            p = (const char*)((tile == 0 ? g_hh : g_hl) + (size_t)(base + rr)*I_DIM);
        } else {
            size_t wr = ((size_t)z*C_DIM + n0 + row)*I_DIM;
            p = (const char*)((tile == 2 ? g_dh : g_dl) + wr);
        }
        lsrc[j] = p; ltile[j] = (uint32_t)tile*TILE_B; lrow[j] = row;
    }
    auto load_stage = [&](int s, int kt){
        uint32_t st = sb + (uint32_t)s*STAGE_D;
        #pragma unroll
        for (int j = 0; j < 2; j++)
            cp_row(st + ltile[j], lsrc[j] + kt*128, lrow[j]);
        cp_commit();
    };

    int mat = lane >> 3;
    uint32_t xm = (uint32_t)(lane & 7) << 4;
    uint32_t rA[4], rB[2];
    #pragma unroll
    for (int mt = 0; mt < 4; mt++)
        rA[mt] = (uint32_t)(warp_m*64 + mt*16 + (mat & 1)*8 + (lane & 7)) << 7;
    #pragma unroll
    for (int ntp = 0; ntp < 2; ntp++)
        rB[ntp] = (uint32_t)(warp_n*32 + ntp*16 + ((mat >> 1) & 1)*8 + (lane & 7)) << 7;
    uint32_t caK = (uint32_t)((mat >> 1) & 1) * 16;
    uint32_t cbK = (uint32_t)(mat & 1) * 16;

    float ac[4][4][4];
    #pragma unroll
    for (int a = 0; a < 4; a++)
        #pragma unroll
        for (int b = 0; b < 4; b++)
            #pragma unroll
            for (int c = 0; c < 4; c++) ac[a][b][c] = 0.f;

    const int KT = I_DIM/64;   // 24
    load_stage(0, 0);
    load_stage(1, 1);

    for (int kt = 0; kt < KT; kt++){
        if (kt + 1 < KT) cp_wait1(); else cp_wait0();
        __syncthreads();
        uint32_t st = sb + (uint32_t)(kt & 1)*STAGE_D;
        uint32_t Ah = st, Al = st + TILE_B;
        uint32_t Bh = st + 2*TILE_B, Bl = st + 3*TILE_B;
        #pragma unroll
        for (int ks = 0; ks < 4; ks++){
            uint32_t cA = ((uint32_t)ks*32 + caK) ^ xm;
            uint32_t cB = ((uint32_t)ks*32 + cbK) ^ xm;
            uint32_t fah[4][4], fal[4][4];
            #pragma unroll
            for (int mt = 0; mt < 4; mt++){
                ldsm4(fah[mt], Ah + rA[mt] + cA);
                ldsm4(fal[mt], Al + rA[mt] + cA);
            }
            uint32_t bh[2][4], bl[2][4];
            #pragma unroll
            for (int p = 0; p < 2; p++){ ldsm4(bh[p], Bh + rB[p] + cB); ldsm4(bl[p], Bl + rB[p] + cB); }
            #pragma unroll
            for (int mt = 0; mt < 4; mt++)
                #pragma unroll
                for (int nt = 0; nt < 4; nt++){
                    const uint32_t* b0 = &bh[nt>>1][(nt&1)*2];
                    const uint32_t* b1 = &bl[nt>>1][(nt&1)*2];
                    hmma(ac[mt][nt], fah[mt], b0);
                    hmma(ac[mt][nt], fah[mt], b1);
                    hmma(ac[mt][nt], fal[mt], b0);
                }
        }
        __syncthreads();
        if (kt + 2 < KT) load_stage(kt & 1, kt + 2);
    }

    int qr = lane >> 2, qc = (lane & 3)*2;
    #pragma unroll
    for (int mt = 0; mt < 4; mt++)
        #pragma unroll
        for (int h2 = 0; h2 < 2; h2++){
            int gr = rb*128 + warp_m*64 + mt*16 + h2*8 + qr;
            if (gr >= cnt) continue;
            size_t slot = (size_t)base + gr;
            float wt = g_wt[slot];
            #pragma unroll
            for (int nt = 0; nt < 4; nt++){
                float2 v;
                v.x = wt * ac[mt][nt][h2*2+0];
                v.y = wt * ac[mt][nt][h2*2+1];
                size_t col = (size_t)n0 + warp_n*32 + nt*8 + qc;
                *(float2*)(g_O + slot*C_DIM + col) = v;
            }
        }
}

__global__ void combine_kernel(float* __restrict__ out){
    int i = blockIdx.x * blockDim.x + threadIdx.x;
    if (i >= N_TOK*(C_DIM/4)) return;
    int t = i / (C_DIM/4), c = (i % (C_DIM/4)) * 4;
    int s0 = g_slot_of[t*2], s1 = g_slot_of[t*2+1];
    float4 a = *(const float4*)&g_O[(size_t)s0*C_DIM + c];
    float4 b = *(const float4*)&g_O[(size_t)s1*C_DIM + c];
    float4 d = *(const float4*)&g_O[(size_t)(2*N_TOK + t)*C_DIM + c];
    float4 r = make_float4(a.x+b.x+d.x, a.y+b.y+d.y, a.z+b.z+d.z, a.w+b.w+d.w);
    *(float4*)&out[(size_t)t*C_DIM + c] = r;
}

// ---------------- launch ----------------
extern "C" void kernel_launch(void* const* d_in, const int* in_sizes, int n_in,
                              void* d_out, int out_size) {
    const float* x    = (const float*)d_in[0];
    const float* wgt  = (const float*)d_in[1];
    const float* bias = (const float*)d_in[2];
    const float* wg   = (const float*)d_in[3];
    const float* wu   = (const float*)d_in[4];
    const float* wd   = (const float*)d_in[5];
    const float* swg  = (const float*)d_in[6];
    const float* swu  = (const float*)d_in[7];
    const float* swd  = (const float*)d_in[8];
    float* out = (float*)d_out;

    cudaFuncSetAttribute(fused_gateup_kernel, cudaFuncAttributeMaxDynamicSharedMemorySize, SMEM_F);
    cudaFuncSetAttribute(down_proj_kernel,    cudaFuncAttributeMaxDynamicSharedMemorySize, SMEM_D);

    init_kernel<<<1, 32>>>();
    router_kernel<<<(N_TOK*32 + 255)/256, 256>>>(x, wgt, bias);
    scan_kernel<<<1, 1>>>();
    fill_kernel<<<(N_TOK + 255)/256, 256>>>();

    split_x_kernel<<<(N_TOK*C_DIM + 255)/256, 256>>>(x);
    dim3 tb(32, 8);
    split_T_kernel<<<dim3(I_DIM/32, C_DIM/32, E_EXP), tb>>>(wg,  0, 0,  C_DIM, I_DIM);
    split_T_kernel<<<dim3(I_DIM/32, C_DIM/32, 1),     tb>>>(swg, 0, 16, C_DIM, I_DIM);
    split_T_kernel<<<dim3(I_DIM/32, C_DIM/32, E_EXP), tb>>>(wu,  1, 0,  C_DIM, I_DIM);
    split_T_kernel<<<dim3(I_DIM/32, C_DIM/32, 1),     tb>>>(swu, 1, 16, C_DIM, I_DIM);
    split_T_kernel<<<dim3(C_DIM/32, I_DIM/32, E_EXP), tb>>>(wd,  2, 0,  I_DIM, C_DIM);
    split_T_kernel<<<dim3(C_DIM/32, I_DIM/32, 1),     tb>>>(swd, 2, 16, I_DIM, C_DIM);

    fused_gateup_kernel<<<dim3(I_DIM/128, N_TOK/128, E_ALL), 256, SMEM_F>>>();
    down_proj_kernel  <<<dim3(C_DIM/128, N_TOK/128, E_ALL), 256, SMEM_D>>>();
    combine_kernel<<<(N_TOK*(C_DIM/4) + 255)/256, 256>>>(out);
}